// round 7
// baseline (speedup 1.0000x reference)
#include <cuda_runtime.h>

// GraphAttention restructured:
//   A  = relu(srcF@src_w+src_b) @ W1[0:128]                (per src node)
//   C  = relu(dstF@dst_w+dst_b) @ W1[256:384] + b1         (per dst node)
//   per edge e=(s,d): distf = relu(dpos@dist_w + dist_b)
//                     h = relu(A[s] + distf@W1[128:256] + C[d]); H[d] += h; deg[d]++
//   agg = dst_enc + H@W2 + deg*b2 ; T = relu(LN(agg))
//   out = relu(T@out_w + out_b + dstF)

#define S_N 16384
#define D_N 16384
#define F   128
#define PAD 132   // 132 floats = 528B, 16B-aligned rows

__device__ float g_src_enc[S_N * F];
__device__ float g_dst_enc[D_N * F];
__device__ float g_Aproj[S_N * F];
__device__ float g_Cproj[D_N * F];
__device__ float g_H[D_N * F];
__device__ float g_agg[D_N * F];
__device__ float g_T[D_N * F];
__device__ int   g_deg[D_N];

// ---------------- shared-tile helpers ----------------

// A row-major [128 x 128] -> As[k*PAD + row] (transposed, k-major)
__device__ __forceinline__ void load_A_transposed(const float* __restrict__ A,
                                                  float* As, int tid) {
    for (int c = tid; c < 128 * 32; c += 256) {
        int kq = c & 31, row = c >> 5;
        float4 v = *reinterpret_cast<const float4*>(A + (size_t)row * 128 + kq * 4);
        As[(kq * 4 + 0) * PAD + row] = v.x;
        As[(kq * 4 + 1) * PAD + row] = v.y;
        As[(kq * 4 + 2) * PAD + row] = v.z;
        As[(kq * 4 + 3) * PAD + row] = v.w;
    }
}

// B rows [64 x 128] row-major -> Bs[k*PAD + col]
__device__ __forceinline__ void load_B_half(const float* __restrict__ B,
                                            float* Bs, int tid) {
    for (int c = tid; c < 64 * 32; c += 256) {
        int colq = c & 31, k = c >> 5;
        *reinterpret_cast<float4*>(Bs + k * PAD + colq * 4) =
            *reinterpret_cast<const float4*>(B + (size_t)k * 128 + colq * 4);
    }
}

// 64-step K loop: acc[8][8] += As[k][ty*8+i] * Bs[k][tx*8+j]
__device__ __forceinline__ void mma_half(const float* __restrict__ As,
                                         const float* __restrict__ Bs,
                                         float acc[8][8], int ty, int tx) {
#pragma unroll 8
    for (int k = 0; k < 64; k++) {
        float4 a0 = *reinterpret_cast<const float4*>(As + k * PAD + ty * 8);
        float4 a1 = *reinterpret_cast<const float4*>(As + k * PAD + ty * 8 + 4);
        float4 b0 = *reinterpret_cast<const float4*>(Bs + k * PAD + tx * 8);
        float4 b1 = *reinterpret_cast<const float4*>(Bs + k * PAD + tx * 8 + 4);
        float a[8] = {a0.x, a0.y, a0.z, a0.w, a1.x, a1.y, a1.z, a1.w};
        float b[8] = {b0.x, b0.y, b0.z, b0.w, b1.x, b1.y, b1.z, b1.w};
#pragma unroll
        for (int i = 0; i < 8; i++)
#pragma unroll
            for (int j = 0; j < 8; j++)
                acc[i][j] = fmaf(a[i], b[j], acc[i][j]);
    }
}

// ---------------- generic 128-wide GEMM with fused epilogue ----------------
// C[row,col] = maybe_relu( A[row,:]@Bw[:,col] + bias[col] + addmat[row,col] + deg[row]*degvec[col] )
extern "C" __global__ void __launch_bounds__(256, 2)
gemm128(const float* __restrict__ A, const float* __restrict__ Bw,
        const float* __restrict__ bias, const float* __restrict__ addmat,
        const int* __restrict__ deg, const float* __restrict__ degvec,
        float* __restrict__ C, int do_relu) {
    extern __shared__ float sm[];
    float* As = sm;                // 128*PAD
    float* Bs = sm + 128 * PAD;    // 64*PAD
    int tid = threadIdx.x;
    int row0 = blockIdx.x * 128;

    load_A_transposed(A + (size_t)row0 * 128, As, tid);
    load_B_half(Bw, Bs, tid);
    __syncthreads();

    float acc[8][8];
#pragma unroll
    for (int i = 0; i < 8; i++)
#pragma unroll
        for (int j = 0; j < 8; j++) acc[i][j] = 0.f;

    int tx = tid & 15, ty = tid >> 4;
    mma_half(As, Bs, acc, ty, tx);
    __syncthreads();
    load_B_half(Bw + 64 * 128, Bs, tid);
    __syncthreads();
    mma_half(As + 64 * PAD, Bs, acc, ty, tx);

#pragma unroll
    for (int i = 0; i < 8; i++) {
        int row = row0 + ty * 8 + i;
#pragma unroll
        for (int j = 0; j < 8; j++) {
            int col = tx * 8 + j;
            float v = acc[i][j];
            if (bias)   v += bias[col];
            if (addmat) v += addmat[(size_t)row * 128 + col];
            if (deg)    v += (float)deg[row] * degvec[col];
            if (do_relu) v = fmaxf(v, 0.f);
            C[(size_t)row * 128 + col] = v;
        }
    }
}

// ---------------- per-edge kernel: distf GEMM + gather + scatter ----------------
extern "C" __global__ void __launch_bounds__(256, 2)
edge_kernel(const float* __restrict__ spos, const float* __restrict__ dpos,
            const int* __restrict__ esrc, const int* __restrict__ edst,
            const float* __restrict__ distw, const float* __restrict__ distb,
            const float* __restrict__ W1b,
            const float* __restrict__ Aproj, const float* __restrict__ Cproj,
            float* __restrict__ H, int* __restrict__ deg, int E) {
    extern __shared__ float sm[];
    float* Dst = sm;                 // distf transposed: [j=128][edge] (PAD)
    float* Bs  = sm + 128 * PAD;     // [64][PAD]
    float* dxs = Bs + 64 * PAD;
    float* dys = dxs + 128;
    float* dw0 = dys + 128;
    float* dw1 = dw0 + 128;
    float* dbv = dw1 + 128;
    int*   sidx = (int*)(dbv + 128);
    int*   didx = sidx + 128;

    int tid = threadIdx.x;
    int e0 = blockIdx.x * 128;

    if (tid < 128) {
        dw0[tid] = distw[tid];
        dw1[tid] = distw[128 + tid];
        dbv[tid] = distb[tid];
        int e = e0 + tid;
        if (e < E) {
            int s = esrc[e], d = edst[e];
            sidx[tid] = s;
            didx[tid] = d;
            float2 sp = *reinterpret_cast<const float2*>(spos + 2 * (size_t)s);
            float2 dp = *reinterpret_cast<const float2*>(dpos + 2 * (size_t)d);
            dxs[tid] = sp.x - dp.x;
            dys[tid] = sp.y - dp.y;
            atomicAdd(&deg[d], 1);
        } else {
            sidx[tid] = 0; didx[tid] = -1;
            dxs[tid] = 0.f; dys[tid] = 0.f;
        }
    }
    load_B_half(W1b, Bs, tid);
    __syncthreads();

    // distf[e][j] = relu(dx*w0[j] + dy*w1[j] + b[j]), stored transposed
    for (int i = tid; i < 128 * 128; i += 256) {
        int j = i >> 7, e = i & 127;
        Dst[j * PAD + e] =
            fmaxf(fmaf(dxs[e], dw0[j], fmaf(dys[e], dw1[j], dbv[j])), 0.f);
    }
    __syncthreads();

    float acc[8][8];
#pragma unroll
    for (int i = 0; i < 8; i++)
#pragma unroll
        for (int j = 0; j < 8; j++) acc[i][j] = 0.f;

    int tx = tid & 15, ty = tid >> 4;
    mma_half(Dst, Bs, acc, ty, tx);
    __syncthreads();
    load_B_half(W1b + 64 * 128, Bs, tid);
    __syncthreads();
    mma_half(Dst + 64 * PAD, Bs, acc, ty, tx);

    // epilogue: h = relu(acc + A[s] + C[d]); H[d] += h
#pragma unroll
    for (int i = 0; i < 8; i++) {
        int el = ty * 8 + i;
        int d = didx[el];
        if (d < 0) continue;
        const float* Ar = Aproj + (size_t)sidx[el] * 128 + tx * 8;
        const float* Cr = Cproj + (size_t)d * 128 + tx * 8;
        float* Hr = H + (size_t)d * 128 + tx * 8;
        float4 a0 = *reinterpret_cast<const float4*>(Ar);
        float4 a1 = *reinterpret_cast<const float4*>(Ar + 4);
        float4 c0 = *reinterpret_cast<const float4*>(Cr);
        float4 c1 = *reinterpret_cast<const float4*>(Cr + 4);
        float add[8] = {a0.x + c0.x, a0.y + c0.y, a0.z + c0.z, a0.w + c0.w,
                        a1.x + c1.x, a1.y + c1.y, a1.z + c1.z, a1.w + c1.w};
#pragma unroll
        for (int j = 0; j < 8; j++) {
            float v = fmaxf(acc[i][j] + add[j], 0.f);
            atomicAdd(Hr + j, v);
        }
    }
}

// ---------------- LayerNorm + ReLU (one warp per row) ----------------
extern "C" __global__ void ln_relu(const float* __restrict__ agg,
                                   const float* __restrict__ g,
                                   const float* __restrict__ b,
                                   float* __restrict__ T) {
    int gw = (blockIdx.x * blockDim.x + threadIdx.x) >> 5;
    int lane = threadIdx.x & 31;
    if (gw >= D_N) return;
    float4 x = reinterpret_cast<const float4*>(agg + (size_t)gw * 128)[lane];
    float s = x.x + x.y + x.z + x.w;
#pragma unroll
    for (int o = 16; o > 0; o >>= 1) s += __shfl_xor_sync(0xffffffffu, s, o);
    float mu = s * (1.f / 128.f);
    float d0 = x.x - mu, d1 = x.y - mu, d2 = x.z - mu, d3 = x.w - mu;
    float q = d0 * d0 + d1 * d1 + d2 * d2 + d3 * d3;
#pragma unroll
    for (int o = 16; o > 0; o >>= 1) q += __shfl_xor_sync(0xffffffffu, q, o);
    float r = rsqrtf(q * (1.f / 128.f) + 1e-5f);
    float4 gg = reinterpret_cast<const float4*>(g)[lane];
    float4 bb = reinterpret_cast<const float4*>(b)[lane];
    float4 y;
    y.x = fmaxf(fmaf(d0 * r, gg.x, bb.x), 0.f);
    y.y = fmaxf(fmaf(d1 * r, gg.y, bb.y), 0.f);
    y.z = fmaxf(fmaf(d2 * r, gg.z, bb.z), 0.f);
    y.w = fmaxf(fmaf(d3 * r, gg.w, bb.w), 0.f);
    reinterpret_cast<float4*>(T + (size_t)gw * 128)[lane] = y;
}

// ---------------- launch ----------------
extern "C" void kernel_launch(void* const* d_in, const int* in_sizes, int n_in,
                              void* d_out, int out_size) {
    const float* srcF   = (const float*)d_in[0];
    const float* spos   = (const float*)d_in[1];
    const float* dstF   = (const float*)d_in[2];
    const float* dpos   = (const float*)d_in[3];
    const float* src_w  = (const float*)d_in[4];
    const float* src_b  = (const float*)d_in[5];
    const float* dst_w  = (const float*)d_in[6];
    const float* dst_b  = (const float*)d_in[7];
    const float* dist_w = (const float*)d_in[8];
    const float* dist_b = (const float*)d_in[9];
    const float* w1     = (const float*)d_in[10];
    const float* b1     = (const float*)d_in[11];
    const float* w2     = (const float*)d_in[12];
    const float* b2     = (const float*)d_in[13];
    const float* lng    = (const float*)d_in[14];
    const float* lnb    = (const float*)d_in[15];
    const float* out_w  = (const float*)d_in[16];
    const float* out_b  = (const float*)d_in[17];
    const int*   esrc   = (const int*)d_in[18];
    const int*   edst   = (const int*)d_in[19];
    int E = in_sizes[18];
    float* out = (float*)d_out;

    float *pSrcEnc, *pDstEnc, *pA, *pC, *pH, *pAgg, *pT;
    int* pDeg;
    cudaGetSymbolAddress((void**)&pSrcEnc, g_src_enc);
    cudaGetSymbolAddress((void**)&pDstEnc, g_dst_enc);
    cudaGetSymbolAddress((void**)&pA, g_Aproj);
    cudaGetSymbolAddress((void**)&pC, g_Cproj);
    cudaGetSymbolAddress((void**)&pH, g_H);
    cudaGetSymbolAddress((void**)&pAgg, g_agg);
    cudaGetSymbolAddress((void**)&pT, g_T);
    cudaGetSymbolAddress((void**)&pDeg, g_deg);

    const int SMEM_G = (128 * PAD + 64 * PAD) * 4;           // 101376 B
    const int SMEM_E = SMEM_G + 7 * 128 * 4;                 // +3584 B
    cudaFuncSetAttribute(gemm128, cudaFuncAttributeMaxDynamicSharedMemorySize, SMEM_E);
    cudaFuncSetAttribute(edge_kernel, cudaFuncAttributeMaxDynamicSharedMemorySize, SMEM_E);

    cudaMemsetAsync(pH, 0, (size_t)D_N * F * sizeof(float));
    cudaMemsetAsync(pDeg, 0, (size_t)D_N * sizeof(int));

    // node encoders + per-node W1 projections
    gemm128<<<128, 256, SMEM_G>>>(srcF, src_w, src_b, nullptr, nullptr, nullptr, pSrcEnc, 1);
    gemm128<<<128, 256, SMEM_G>>>(pSrcEnc, w1, nullptr, nullptr, nullptr, nullptr, pA, 0);
    gemm128<<<128, 256, SMEM_G>>>(dstF, dst_w, dst_b, nullptr, nullptr, nullptr, pDstEnc, 1);
    gemm128<<<128, 256, SMEM_G>>>(pDstEnc, w1 + 256 * 128, b1, nullptr, nullptr, nullptr, pC, 0);

    // per-edge hidden + scatter
    int nb = (E + 127) / 128;
    edge_kernel<<<nb, 256, SMEM_E>>>(spos, dpos, esrc, edst, dist_w, dist_b,
                                     w1 + 128 * 128, pA, pC, pH, pDeg, E);

    // agg = dst_enc + H@W2 + deg*b2 ; LN+relu ; out = relu(T@out_w + out_b + dstF)
    gemm128<<<128, 256, SMEM_G>>>(pH, w2, nullptr, pDstEnc, pDeg, b2, pAgg, 0);
    ln_relu<<<D_N / 8, 256>>>(pAgg, lng, lnb, pT);
    gemm128<<<128, 256, SMEM_G>>>(pT, out_w, out_b, dstF, nullptr, nullptr, out, 1);
}

// round 8
// speedup vs baseline: 1.8849x; 1.8849x over previous
#include <cuda_runtime.h>
#include <cstdint>

// GraphAttention restructured:
//   A  = relu(srcF@src_w+src_b) @ W1[0:128]                (per src node)
//   C  = relu(dstF@dst_w+dst_b) @ W1[256:384] + b1         (per dst node)
//   per edge e=(s,d): distf = relu(dpos@dist_w + dist_b)
//                     h = relu(A[s] + distf@W1[128:256] + C[d]); H[d] += h; deg[d]++
//   agg = dst_enc + H@W2 + deg*b2 ; T = relu(LN(agg))
//   out = relu(T@out_w + out_b + dstF)
//
// R7: edge kernel rewritten on mma.sync.m16n8k8.tf32 (tensor pipe), distf
// computed directly into A-fragments (no smem staging), conflict-free B
// fragment layout, and red.global.add.v4.f32 scatter (4x fewer atomic lanes).

#define S_N 16384
#define D_N 16384
#define F   128
#define PAD 132   // 132 floats = 528B, 16B-aligned rows

__device__ float g_src_enc[S_N * F];
__device__ float g_dst_enc[D_N * F];
__device__ float g_Aproj[S_N * F];
__device__ float g_Cproj[D_N * F];
__device__ float g_H[D_N * F];
__device__ float g_agg[D_N * F];
__device__ float g_T[D_N * F];
__device__ int   g_deg[D_N];

// ---------------- tf32 helpers ----------------
__device__ __forceinline__ uint32_t f2tf32(float x) {
    uint32_t r;
    asm("cvt.rna.tf32.f32 %0, %1;" : "=r"(r) : "f"(x));
    return r;
}

__device__ __forceinline__ void mma_tf32(float c[4], uint32_t a0, uint32_t a1,
                                         uint32_t a2, uint32_t a3,
                                         uint32_t b0, uint32_t b1) {
    asm volatile(
        "mma.sync.aligned.m16n8k8.row.col.f32.tf32.tf32.f32 "
        "{%0,%1,%2,%3}, {%4,%5,%6,%7}, {%8,%9}, {%0,%1,%2,%3};"
        : "+f"(c[0]), "+f"(c[1]), "+f"(c[2]), "+f"(c[3])
        : "r"(a0), "r"(a1), "r"(a2), "r"(a3), "r"(b0), "r"(b1));
}

// ---------------- shared-tile helpers (node GEMMs, unchanged) ----------------

__device__ __forceinline__ void load_A_transposed(const float* __restrict__ A,
                                                  float* As, int tid) {
    for (int c = tid; c < 128 * 32; c += 256) {
        int kq = c & 31, row = c >> 5;
        float4 v = *reinterpret_cast<const float4*>(A + (size_t)row * 128 + kq * 4);
        As[(kq * 4 + 0) * PAD + row] = v.x;
        As[(kq * 4 + 1) * PAD + row] = v.y;
        As[(kq * 4 + 2) * PAD + row] = v.z;
        As[(kq * 4 + 3) * PAD + row] = v.w;
    }
}

__device__ __forceinline__ void load_B_half(const float* __restrict__ B,
                                            float* Bs, int tid) {
    for (int c = tid; c < 64 * 32; c += 256) {
        int colq = c & 31, k = c >> 5;
        *reinterpret_cast<float4*>(Bs + k * PAD + colq * 4) =
            *reinterpret_cast<const float4*>(B + (size_t)k * 128 + colq * 4);
    }
}

__device__ __forceinline__ void mma_half(const float* __restrict__ As,
                                         const float* __restrict__ Bs,
                                         float acc[8][8], int ty, int tx) {
#pragma unroll 8
    for (int k = 0; k < 64; k++) {
        float4 a0 = *reinterpret_cast<const float4*>(As + k * PAD + ty * 8);
        float4 a1 = *reinterpret_cast<const float4*>(As + k * PAD + ty * 8 + 4);
        float4 b0 = *reinterpret_cast<const float4*>(Bs + k * PAD + tx * 8);
        float4 b1 = *reinterpret_cast<const float4*>(Bs + k * PAD + tx * 8 + 4);
        float a[8] = {a0.x, a0.y, a0.z, a0.w, a1.x, a1.y, a1.z, a1.w};
        float b[8] = {b0.x, b0.y, b0.z, b0.w, b1.x, b1.y, b1.z, b1.w};
#pragma unroll
        for (int i = 0; i < 8; i++)
#pragma unroll
            for (int j = 0; j < 8; j++)
                acc[i][j] = fmaf(a[i], b[j], acc[i][j]);
    }
}

// ---------------- generic 128-wide GEMM with fused epilogue ----------------
extern "C" __global__ void __launch_bounds__(256, 2)
gemm128(const float* __restrict__ A, const float* __restrict__ Bw,
        const float* __restrict__ bias, const float* __restrict__ addmat,
        const int* __restrict__ deg, const float* __restrict__ degvec,
        float* __restrict__ C, int do_relu) {
    extern __shared__ float sm[];
    float* As = sm;                // 128*PAD
    float* Bs = sm + 128 * PAD;    // 64*PAD
    int tid = threadIdx.x;
    int row0 = blockIdx.x * 128;

    load_A_transposed(A + (size_t)row0 * 128, As, tid);
    load_B_half(Bw, Bs, tid);
    __syncthreads();

    float acc[8][8];
#pragma unroll
    for (int i = 0; i < 8; i++)
#pragma unroll
        for (int j = 0; j < 8; j++) acc[i][j] = 0.f;

    int tx = tid & 15, ty = tid >> 4;
    mma_half(As, Bs, acc, ty, tx);
    __syncthreads();
    load_B_half(Bw + 64 * 128, Bs, tid);
    __syncthreads();
    mma_half(As + 64 * PAD, Bs, acc, ty, tx);

#pragma unroll
    for (int i = 0; i < 8; i++) {
        int row = row0 + ty * 8 + i;
#pragma unroll
        for (int j = 0; j < 8; j++) {
            int col = tx * 8 + j;
            float v = acc[i][j];
            if (bias)   v += bias[col];
            if (addmat) v += addmat[(size_t)row * 128 + col];
            if (deg)    v += (float)deg[row] * degvec[col];
            if (do_relu) v = fmaxf(v, 0.f);
            C[(size_t)row * 128 + col] = v;
        }
    }
}

// ---------------- per-edge kernel: tf32 tensor-core GEMM + gather + scatter ----
// Block: 256 threads = 8 warps; 128 edges per block; each warp owns a 16-edge
// M-tile and the full N=128. K=128 in 16 chunks of 8.
//
// A fragment (distf) is computed on the fly from (dx,dy).
// B (W1b, tf32-rounded) smem layout: plane p in {0,1} (k%8<4 / >=4),
//   word index = ((p*16 + kc)*128 + n)*4 + (k%4)  -> warp load addr = base+laneid
//   (conflict-free).
extern "C" __global__ void __launch_bounds__(256, 2)
edge_kernel(const float* __restrict__ spos, const float* __restrict__ dpos,
            const int* __restrict__ esrc, const int* __restrict__ edst,
            const float* __restrict__ distw, const float* __restrict__ distb,
            const float* __restrict__ W1b,
            const float* __restrict__ Aproj, const float* __restrict__ Cproj,
            float* __restrict__ H, int* __restrict__ deg, int E) {
    extern __shared__ uint32_t smu[];
    uint32_t* Bs  = smu;                          // 2*16*128*4 = 16384 words
    float*    w0r = (float*)(smu + 16384);        // 128
    float*    w1r = w0r + 128;                    // 128
    float*    br  = w1r + 128;                    // 128
    float*    dxs = br + 128;                     // 128
    float*    dys = dxs + 128;                    // 128
    int*      sidx = (int*)(dys + 128);           // 128
    int*      didx = sidx + 128;                  // 128

    int tid = threadIdx.x;
    int e0 = blockIdx.x * 128;

    if (tid < 128) {
        int e = e0 + tid;
        if (e < E) {
            int s = esrc[e], d = edst[e];
            sidx[tid] = s;
            didx[tid] = d;
            float2 sp = *reinterpret_cast<const float2*>(spos + 2 * (size_t)s);
            float2 dp = *reinterpret_cast<const float2*>(dpos + 2 * (size_t)d);
            dxs[tid] = sp.x - dp.x;
            dys[tid] = sp.y - dp.y;
            atomicAdd(&deg[d], 1);
        } else {
            sidx[tid] = 0; didx[tid] = -1;
            dxs[tid] = 0.f; dys[tid] = 0.f;
        }
    } else {
        int t = tid - 128;
        w0r[t] = distw[t];
        w1r[t] = distw[128 + t];
        br[t]  = distb[t];
    }

    // Fill B tiles (tf32-rounded W1b) — coalesced gmem reads (L2-resident).
    for (int idx = tid; idx < 128 * 128; idx += 256) {
        int k = idx >> 7, n = idx & 127;
        int kc = k >> 3, kk7 = k & 7;
        int p = kk7 >> 2, kk = kk7 & 3;
        Bs[(((p * 16 + kc) * 128 + n) << 2) + kk] = f2tf32(W1b[(size_t)k * 128 + n]);
    }
    __syncthreads();

    int lane = tid & 31;
    int warp = tid >> 5;
    int g   = lane >> 2;   // group id 0..7
    int tig = lane & 3;    // thread-in-group 0..3
    int rA = warp * 16 + g;      // local edge row (fragment rows g / g+8)
    int rB = rA + 8;

    float dx0 = dxs[rA], dy0 = dys[rA];
    float dx1 = dxs[rB], dy1 = dys[rB];

    float acc[16][4];
#pragma unroll
    for (int nt = 0; nt < 16; nt++)
#pragma unroll
        for (int j = 0; j < 4; j++) acc[nt][j] = 0.f;

#pragma unroll
    for (int kc = 0; kc < 16; kc++) {
        int k0 = kc * 8 + tig, k1 = k0 + 4;
        float w00 = w0r[k0], w10 = w1r[k0], bb0 = br[k0];
        float w01 = w0r[k1], w11 = w1r[k1], bb1 = br[k1];
        uint32_t a0 = f2tf32(fmaxf(fmaf(dx0, w00, fmaf(dy0, w10, bb0)), 0.f));
        uint32_t a1 = f2tf32(fmaxf(fmaf(dx1, w00, fmaf(dy1, w10, bb0)), 0.f));
        uint32_t a2 = f2tf32(fmaxf(fmaf(dx0, w01, fmaf(dy0, w11, bb1)), 0.f));
        uint32_t a3 = f2tf32(fmaxf(fmaf(dx1, w01, fmaf(dy1, w11, bb1)), 0.f));
        const uint32_t* B0 = Bs + ((kc * 128) << 2) + tig;
        const uint32_t* B1 = Bs + (((16 + kc) * 128) << 2) + tig;
#pragma unroll
        for (int nt = 0; nt < 16; nt++) {
            uint32_t b0 = B0[((nt * 8 + g) << 2)];
            uint32_t b1 = B1[((nt * 8 + g) << 2)];
            mma_tf32(acc[nt], a0, a1, a2, a3, b0, b1);
        }
    }

    // Epilogue: pair up lanes (lane^1) so each thread owns 4 consecutive cols
    // of ONE row (even tig -> row rA, odd tig -> row rB), then relu(+A+C) and
    // one red.global.add.v4.f32 per 4 columns.
    int myrow = (tig & 1) ? rB : rA;
    int d = didx[myrow];
    int s = sidx[myrow];
    int colb0 = (tig & ~1) * 2;   // 0 or 4

    const float4* Ar = reinterpret_cast<const float4*>(Aproj + (size_t)s * 128);
    const float4* Cr = reinterpret_cast<const float4*>(Cproj + (size_t)(d < 0 ? 0 : d) * 128);
    float* Hr = H + (size_t)(d < 0 ? 0 : d) * 128;

#pragma unroll
    for (int nt = 0; nt < 16; nt++) {
        float c0 = acc[nt][0], c1 = acc[nt][1], c2 = acc[nt][2], c3 = acc[nt][3];
        float o0 = __shfl_xor_sync(0xffffffffu, c0, 1);
        float o1 = __shfl_xor_sync(0xffffffffu, c1, 1);
        float o2 = __shfl_xor_sync(0xffffffffu, c2, 1);
        float o3 = __shfl_xor_sync(0xffffffffu, c3, 1);
        if (d < 0) continue;
        float v0, v1, v2, v3;
        if (tig & 1) { v0 = o2; v1 = o3; v2 = c2; v3 = c3; }
        else         { v0 = c0; v1 = c1; v2 = o0; v3 = o1; }
        int col = colb0 + nt * 8;
        float4 av = Ar[col >> 2];
        float4 cv = Cr[col >> 2];
        v0 = fmaxf(v0 + av.x + cv.x, 0.f);
        v1 = fmaxf(v1 + av.y + cv.y, 0.f);
        v2 = fmaxf(v2 + av.z + cv.z, 0.f);
        v3 = fmaxf(v3 + av.w + cv.w, 0.f);
        asm volatile("red.global.add.v4.f32 [%0], {%1,%2,%3,%4};"
                     :: "l"(Hr + col), "f"(v0), "f"(v1), "f"(v2), "f"(v3)
                     : "memory");
    }
}

// ---------------- LayerNorm + ReLU (one warp per row) ----------------
extern "C" __global__ void ln_relu(const float* __restrict__ agg,
                                   const float* __restrict__ g,
                                   const float* __restrict__ b,
                                   float* __restrict__ T) {
    int gw = (blockIdx.x * blockDim.x + threadIdx.x) >> 5;
    int lane = threadIdx.x & 31;
    if (gw >= D_N) return;
    float4 x = reinterpret_cast<const float4*>(agg + (size_t)gw * 128)[lane];
    float s = x.x + x.y + x.z + x.w;
#pragma unroll
    for (int o = 16; o > 0; o >>= 1) s += __shfl_xor_sync(0xffffffffu, s, o);
    float mu = s * (1.f / 128.f);
    float d0 = x.x - mu, d1 = x.y - mu, d2 = x.z - mu, d3 = x.w - mu;
    float q = d0 * d0 + d1 * d1 + d2 * d2 + d3 * d3;
#pragma unroll
    for (int o = 16; o > 0; o >>= 1) q += __shfl_xor_sync(0xffffffffu, q, o);
    float r = rsqrtf(q * (1.f / 128.f) + 1e-5f);
    float4 gg = reinterpret_cast<const float4*>(g)[lane];
    float4 bb = reinterpret_cast<const float4*>(b)[lane];
    float4 y;
    y.x = fmaxf(fmaf(d0 * r, gg.x, bb.x), 0.f);
    y.y = fmaxf(fmaf(d1 * r, gg.y, bb.y), 0.f);
    y.z = fmaxf(fmaf(d2 * r, gg.z, bb.z), 0.f);
    y.w = fmaxf(fmaf(d3 * r, gg.w, bb.w), 0.f);
    reinterpret_cast<float4*>(T + (size_t)gw * 128)[lane] = y;
}

// ---------------- launch ----------------
extern "C" void kernel_launch(void* const* d_in, const int* in_sizes, int n_in,
                              void* d_out, int out_size) {
    const float* srcF   = (const float*)d_in[0];
    const float* spos   = (const float*)d_in[1];
    const float* dstF   = (const float*)d_in[2];
    const float* dpos   = (const float*)d_in[3];
    const float* src_w  = (const float*)d_in[4];
    const float* src_b  = (const float*)d_in[5];
    const float* dst_w  = (const float*)d_in[6];
    const float* dst_b  = (const float*)d_in[7];
    const float* dist_w = (const float*)d_in[8];
    const float* dist_b = (const float*)d_in[9];
    const float* w1     = (const float*)d_in[10];
    const float* b1     = (const float*)d_in[11];
    const float* w2     = (const float*)d_in[12];
    const float* b2     = (const float*)d_in[13];
    const float* lng    = (const float*)d_in[14];
    const float* lnb    = (const float*)d_in[15];
    const float* out_w  = (const float*)d_in[16];
    const float* out_b  = (const float*)d_in[17];
    const int*   esrc   = (const int*)d_in[18];
    const int*   edst   = (const int*)d_in[19];
    int E = in_sizes[18];
    float* out = (float*)d_out;

    float *pSrcEnc, *pDstEnc, *pA, *pC, *pH, *pAgg, *pT;
    int* pDeg;
    cudaGetSymbolAddress((void**)&pSrcEnc, g_src_enc);
    cudaGetSymbolAddress((void**)&pDstEnc, g_dst_enc);
    cudaGetSymbolAddress((void**)&pA, g_Aproj);
    cudaGetSymbolAddress((void**)&pC, g_Cproj);
    cudaGetSymbolAddress((void**)&pH, g_H);
    cudaGetSymbolAddress((void**)&pAgg, g_agg);
    cudaGetSymbolAddress((void**)&pT, g_T);
    cudaGetSymbolAddress((void**)&pDeg, g_deg);

    const int SMEM_G = (128 * PAD + 64 * PAD) * 4;            // 101376 B
    const int SMEM_E = (16384 + 7 * 128) * 4;                 // 69120 B
    cudaFuncSetAttribute(gemm128, cudaFuncAttributeMaxDynamicSharedMemorySize, SMEM_G);
    cudaFuncSetAttribute(edge_kernel, cudaFuncAttributeMaxDynamicSharedMemorySize, SMEM_E);

    cudaMemsetAsync(pH, 0, (size_t)D_N * F * sizeof(float));
    cudaMemsetAsync(pDeg, 0, (size_t)D_N * sizeof(int));

    // node encoders + per-node W1 projections
    gemm128<<<128, 256, SMEM_G>>>(srcF, src_w, src_b, nullptr, nullptr, nullptr, pSrcEnc, 1);
    gemm128<<<128, 256, SMEM_G>>>(pSrcEnc, w1, nullptr, nullptr, nullptr, nullptr, pA, 0);
    gemm128<<<128, 256, SMEM_G>>>(dstF, dst_w, dst_b, nullptr, nullptr, nullptr, pDstEnc, 1);
    gemm128<<<128, 256, SMEM_G>>>(pDstEnc, w1 + 256 * 128, b1, nullptr, nullptr, nullptr, pC, 0);

    // per-edge hidden + scatter (tf32 tensor cores)
    int nb = (E + 127) / 128;
    edge_kernel<<<nb, 256, SMEM_E>>>(spos, dpos, esrc, edst, dist_w, dist_b,
                                     w1 + 128 * 128, pA, pC, pH, pDeg, E);

    // agg = dst_enc + H@W2 + deg*b2 ; LN+relu ; out = relu(T@out_w + out_b + dstF)
    gemm128<<<128, 256, SMEM_G>>>(pH, w2, nullptr, pDstEnc, pDeg, b2, pAgg, 0);
    ln_relu<<<D_N / 8, 256>>>(pAgg, lng, lnb, pT);
    gemm128<<<128, 256, SMEM_G>>>(pT, out_w, out_b, dstF, nullptr, nullptr, out, 1);
}

// round 9
// speedup vs baseline: 3.1127x; 1.6514x over previous
#include <cuda_runtime.h>
#include <cstdint>

// GraphAttention restructured (R8):
//   A  = relu(srcF@src_w+src_b) @ W1[0:128]            (fused2, per src node)
//   dstEnc = relu(dstF@dst_w+dst_b); C = dstEnc@W1[256:384] + b1   (fused2)
//   per edge e=(s,d): distf = relu(dpos@dist_w + dist_b)
//                     h = relu(A[s] + distf@W1[128:256] + C[d]); H[d]+=h; deg[d]++
//   out = relu( relu(LN(H@W2 + dstEnc + deg*b2)) @ out_w + out_b + dstF )  (fused2)
//
// All GEMMs on mma.sync.m16n8k8.tf32. Node GEMMs fused two-stages-per-kernel
// with the intermediate (and LayerNorm) living in shared memory.

#define S_N 16384
#define D_N 16384
#define F   128
#define PADH 68    // half-row pad: 64+4 floats

__device__ float g_dst_enc[D_N * F];
__device__ float g_Aproj[S_N * F];
__device__ float g_Cproj[D_N * F];
__device__ float g_H[D_N * F];
__device__ int   g_deg[D_N];
__device__ uint32_t g_W1frag[16384];   // edge-layout tf32 fragment of W1[128:256]

// ---------------- tf32 helpers ----------------
__device__ __forceinline__ uint32_t f2tf32(float x) {
    uint32_t r;
    asm("cvt.rna.tf32.f32 %0, %1;" : "=r"(r) : "f"(x));
    return r;
}

__device__ __forceinline__ void mma_tf32(float c[4], uint32_t a0, uint32_t a1,
                                         uint32_t a2, uint32_t a3,
                                         uint32_t b0, uint32_t b1) {
    asm volatile(
        "mma.sync.aligned.m16n8k8.row.col.f32.tf32.tf32.f32 "
        "{%0,%1,%2,%3}, {%4,%5,%6,%7}, {%8,%9}, {%0,%1,%2,%3};"
        : "+f"(c[0]), "+f"(c[1]), "+f"(c[2]), "+f"(c[3])
        : "r"(a0), "r"(a1), "r"(a2), "r"(a3), "r"(b0), "r"(b1));
}

// ---------------- W1b fragment precompute (edge-kernel layout) ----------------
extern "C" __global__ void prep_w1b(const float* __restrict__ W1b,
                                    uint32_t* __restrict__ frag) {
    int idx = blockIdx.x * 256 + threadIdx.x;   // 16384 total
    int k = idx >> 7, n = idx & 127;
    int kc = k >> 3, kk7 = k & 7;
    int p = kk7 >> 2, kk = kk7 & 3;
    frag[(((p * 16 + kc) * 128 + n) << 2) + kk] = f2tf32(W1b[idx]);
}

// ---------------- fused 2-stage node GEMM ----------------
// out = ep2( ep1( X@B1 ) @ B2 )
//   ep1: +bias1 / +add1[row] / +deg[row]*degv / relu1 / optional global write wS1
//        / optional LayerNorm+relu between stages
//   ep2: +bias2 / +add2[row] / relu2
// Block 256 (8 warps), CTA = 128 rows x 128 cols, K=128.
// smem: buf0/buf1 = two K-halves of the stage A operand, row-major r*PADH+k,
//       Bs = tf32 B fragment, interleaved so one LDS.64 yields (b0,b1).

__device__ __forceinline__ void stage_B_frag(const float* __restrict__ B,
                                             uint32_t* __restrict__ Bs, int tid) {
    // pair index p = kc*128+n ; words [p*8 .. p*8+7], word j holds k=kc*8+(j&1)*4+(j>>1)
    for (int i = 0; i < 8; i++) {
        int p = tid + i * 256;
        int kc = p >> 7, n = p & 127;
        const float* bp = B + (size_t)(kc * 8) * 128 + n;
        uint32_t v[8];
#pragma unroll
        for (int j = 0; j < 8; j++)
            v[j] = f2tf32(bp[(((j & 1) << 2) + (j >> 1)) * 128]);
        uint4* d = reinterpret_cast<uint4*>(Bs + p * 8);
        d[0] = make_uint4(v[0], v[1], v[2], v[3]);
        d[1] = make_uint4(v[4], v[5], v[6], v[7]);
    }
}

__device__ __forceinline__ void mainloop_tc(const float* __restrict__ buf0,
                                            const float* __restrict__ buf1,
                                            const uint32_t* __restrict__ Bs,
                                            float acc[2][8][4],
                                            int warp, int lane) {
    int g = lane >> 2, tig = lane & 3;
    int mrow = (warp & 3) * 32;
    int nbase = (warp >> 2) * 64;
    const uint2* B2p = reinterpret_cast<const uint2*>(Bs);
#pragma unroll
    for (int kc = 0; kc < 16; kc++) {
        const float* bh = (kc < 8) ? buf0 : buf1;
        int k0 = (kc & 7) * 8 + tig;
        uint32_t a[2][4];
#pragma unroll
        for (int mt = 0; mt < 2; mt++) {
            int r = mrow + mt * 16 + g;
            a[mt][0] = f2tf32(bh[r * PADH + k0]);
            a[mt][1] = f2tf32(bh[(r + 8) * PADH + k0]);
            a[mt][2] = f2tf32(bh[r * PADH + k0 + 4]);
            a[mt][3] = f2tf32(bh[(r + 8) * PADH + k0 + 4]);
        }
#pragma unroll
        for (int nt = 0; nt < 8; nt++) {
            int n = nbase + nt * 8 + g;
            uint2 bb = B2p[(kc * 128 + n) * 4 + tig];
            mma_tf32(acc[0][nt], a[0][0], a[0][1], a[0][2], a[0][3], bb.x, bb.y);
            mma_tf32(acc[1][nt], a[1][0], a[1][1], a[1][2], a[1][3], bb.x, bb.y);
        }
    }
}

extern "C" __global__ void __launch_bounds__(256, 1)
fused2(const float* __restrict__ X, const float* __restrict__ B1,
       const float* __restrict__ bias1, const float* __restrict__ add1,
       const int* __restrict__ deg, const float* __restrict__ degv,
       int relu1, float* __restrict__ wS1,
       int do_ln, const float* __restrict__ lng, const float* __restrict__ lnb,
       const float* __restrict__ B2, const float* __restrict__ bias2,
       const float* __restrict__ add2, int relu2, float* __restrict__ out) {
    extern __shared__ float sm[];
    float* buf0 = sm;                       // 128*PADH
    float* buf1 = sm + 128 * PADH;          // 128*PADH
    uint32_t* Bs = reinterpret_cast<uint32_t*>(sm + 2 * 128 * PADH);  // 16384

    int tid = threadIdx.x;
    int lane = tid & 31, warp = tid >> 5;
    int row0 = blockIdx.x * 128;

    // stage A tile (both halves) + B1 fragment
    {
        const float* Xp = X + (size_t)row0 * 128;
        for (int i = 0; i < 16; i++) {
            int idx = tid + i * 256;          // 4096 float4s
            int row = idx >> 5, q = idx & 31;
            float4 v = *reinterpret_cast<const float4*>(Xp + (size_t)row * 128 + q * 4);
            float* d = (q < 16 ? buf0 : buf1) + row * PADH + (q & 15) * 4;
            *reinterpret_cast<float4*>(d) = v;
        }
    }
    stage_B_frag(B1, Bs, tid);
    __syncthreads();

    float acc[2][8][4];
#pragma unroll
    for (int mt = 0; mt < 2; mt++)
#pragma unroll
        for (int nt = 0; nt < 8; nt++)
#pragma unroll
            for (int j = 0; j < 4; j++) acc[mt][nt][j] = 0.f;

    mainloop_tc(buf0, buf1, Bs, acc, warp, lane);
    __syncthreads();

    // stage-1 epilogue -> bufs (+ optional global write), restage Bs=B2
    {
        int g = lane >> 2, tig = lane & 3;
        int mrow = (warp & 3) * 32;
        int nbase = (warp >> 2) * 64;
#pragma unroll
        for (int mt = 0; mt < 2; mt++) {
#pragma unroll
            for (int nt = 0; nt < 8; nt++) {
                int col = nbase + nt * 8 + 2 * tig;
#pragma unroll
                for (int half = 0; half < 2; half++) {   // c0,c1 vs c2,c3
                    int r = mrow + mt * 16 + g + half * 8;
                    float v0 = acc[mt][nt][half * 2];
                    float v1 = acc[mt][nt][half * 2 + 1];
                    if (bias1) { v0 += bias1[col]; v1 += bias1[col + 1]; }
                    if (add1) {
                        float2 av = *reinterpret_cast<const float2*>(
                            add1 + (size_t)(row0 + r) * 128 + col);
                        v0 += av.x; v1 += av.y;
                    }
                    if (deg) {
                        float dv = (float)deg[row0 + r];
                        v0 += dv * degv[col]; v1 += dv * degv[col + 1];
                    }
                    if (relu1) { v0 = fmaxf(v0, 0.f); v1 = fmaxf(v1, 0.f); }
                    float* bp = (col < 64 ? buf0 : buf1) + r * PADH + (col & 63);
                    bp[0] = v0; bp[1] = v1;
                    if (wS1) {
                        *reinterpret_cast<float2*>(wS1 + (size_t)(row0 + r) * 128 + col) =
                            make_float2(v0, v1);
                    }
                }
            }
        }
    }
    stage_B_frag(B2, Bs, tid);
    __syncthreads();

    if (do_ln) {
        int r = tid >> 1, h = tid & 1;
        float* bp = (h ? buf1 : buf0) + r * PADH;
        float s = 0.f;
#pragma unroll 8
        for (int j = 0; j < 64; j++) s += bp[j];
        s += __shfl_xor_sync(0xffffffffu, s, 1);
        float mu = s * (1.f / 128.f);
        float q = 0.f;
#pragma unroll 8
        for (int j = 0; j < 64; j++) { float d = bp[j] - mu; q += d * d; }
        q += __shfl_xor_sync(0xffffffffu, q, 1);
        float rs = rsqrtf(q * (1.f / 128.f) + 1e-5f);
#pragma unroll 8
        for (int j = 0; j < 64; j++) {
            int col = h * 64 + j;
            bp[j] = fmaxf(fmaf((bp[j] - mu) * rs, lng[col], lnb[col]), 0.f);
        }
        __syncthreads();
    }

#pragma unroll
    for (int mt = 0; mt < 2; mt++)
#pragma unroll
        for (int nt = 0; nt < 8; nt++)
#pragma unroll
            for (int j = 0; j < 4; j++) acc[mt][nt][j] = 0.f;

    mainloop_tc(buf0, buf1, Bs, acc, warp, lane);

    // stage-2 epilogue -> out
    {
        int g = lane >> 2, tig = lane & 3;
        int mrow = (warp & 3) * 32;
        int nbase = (warp >> 2) * 64;
#pragma unroll
        for (int mt = 0; mt < 2; mt++) {
#pragma unroll
            for (int nt = 0; nt < 8; nt++) {
                int col = nbase + nt * 8 + 2 * tig;
#pragma unroll
                for (int half = 0; half < 2; half++) {
                    int r = mrow + mt * 16 + g + half * 8;
                    float v0 = acc[mt][nt][half * 2];
                    float v1 = acc[mt][nt][half * 2 + 1];
                    if (bias2) { v0 += bias2[col]; v1 += bias2[col + 1]; }
                    if (add2) {
                        float2 av = *reinterpret_cast<const float2*>(
                            add2 + (size_t)(row0 + r) * 128 + col);
                        v0 += av.x; v1 += av.y;
                    }
                    if (relu2) { v0 = fmaxf(v0, 0.f); v1 = fmaxf(v1, 0.f); }
                    *reinterpret_cast<float2*>(out + (size_t)(row0 + r) * 128 + col) =
                        make_float2(v0, v1);
                }
            }
        }
    }
}

// ---------------- per-edge kernel (R7 core, prestaged B fragment) ----------------
extern "C" __global__ void __launch_bounds__(256, 2)
edge_kernel(const float* __restrict__ spos, const float* __restrict__ dpos,
            const int* __restrict__ esrc, const int* __restrict__ edst,
            const float* __restrict__ distw, const float* __restrict__ distb,
            const uint32_t* __restrict__ W1frag,
            const float* __restrict__ Aproj, const float* __restrict__ Cproj,
            float* __restrict__ H, int* __restrict__ deg, int E) {
    extern __shared__ uint32_t smu[];
    uint32_t* Bs  = smu;                          // 16384 words
    float*    w0r = (float*)(smu + 16384);        // 128
    float*    w1r = w0r + 128;
    float*    br  = w1r + 128;
    float*    dxs = br + 128;
    float*    dys = dxs + 128;
    int*      sidx = (int*)(dys + 128);
    int*      didx = sidx + 128;

    int tid = threadIdx.x;
    int e0 = blockIdx.x * 128;

    if (tid < 128) {
        int e = e0 + tid;
        if (e < E) {
            int s = esrc[e], d = edst[e];
            sidx[tid] = s;
            didx[tid] = d;
            float2 sp = *reinterpret_cast<const float2*>(spos + 2 * (size_t)s);
            float2 dp = *reinterpret_cast<const float2*>(dpos + 2 * (size_t)d);
            dxs[tid] = sp.x - dp.x;
            dys[tid] = sp.y - dp.y;
            atomicAdd(&deg[d], 1);
        } else {
            sidx[tid] = 0; didx[tid] = -1;
            dxs[tid] = 0.f; dys[tid] = 0.f;
        }
    } else {
        int t = tid - 128;
        w0r[t] = distw[t];
        w1r[t] = distw[128 + t];
        br[t]  = distb[t];
    }

    // copy prestaged tf32 fragment (16 uint4 per thread, fully coalesced)
    {
        const uint4* s4 = reinterpret_cast<const uint4*>(W1frag);
        uint4* d4 = reinterpret_cast<uint4*>(Bs);
        for (int i = tid; i < 4096; i += 256) d4[i] = s4[i];
    }
    __syncthreads();

    int lane = tid & 31;
    int warp = tid >> 5;
    int g   = lane >> 2;
    int tig = lane & 3;
    int rA = warp * 16 + g;
    int rB = rA + 8;

    float dx0 = dxs[rA], dy0 = dys[rA];
    float dx1 = dxs[rB], dy1 = dys[rB];

    float acc[16][4];
#pragma unroll
    for (int nt = 0; nt < 16; nt++)
#pragma unroll
        for (int j = 0; j < 4; j++) acc[nt][j] = 0.f;

#pragma unroll
    for (int kc = 0; kc < 16; kc++) {
        int k0 = kc * 8 + tig, k1 = k0 + 4;
        float w00 = w0r[k0], w10 = w1r[k0], bb0 = br[k0];
        float w01 = w0r[k1], w11 = w1r[k1], bb1 = br[k1];
        uint32_t a0 = f2tf32(fmaxf(fmaf(dx0, w00, fmaf(dy0, w10, bb0)), 0.f));
        uint32_t a1 = f2tf32(fmaxf(fmaf(dx1, w00, fmaf(dy1, w10, bb0)), 0.f));
        uint32_t a2 = f2tf32(fmaxf(fmaf(dx0, w01, fmaf(dy0, w11, bb1)), 0.f));
        uint32_t a3 = f2tf32(fmaxf(fmaf(dx1, w01, fmaf(dy1, w11, bb1)), 0.f));
        const uint32_t* B0 = Bs + ((kc * 128) << 2) + tig;
        const uint32_t* B1 = Bs + (((16 + kc) * 128) << 2) + tig;
#pragma unroll
        for (int nt = 0; nt < 16; nt++) {
            uint32_t b0 = B0[((nt * 8 + g) << 2)];
            uint32_t b1 = B1[((nt * 8 + g) << 2)];
            mma_tf32(acc[nt], a0, a1, a2, a3, b0, b1);
        }
    }

    int myrow = (tig & 1) ? rB : rA;
    int d = didx[myrow];
    int s = sidx[myrow];
    int colb0 = (tig & ~1) * 2;

    const float4* Ar = reinterpret_cast<const float4*>(Aproj + (size_t)s * 128);
    const float4* Cr = reinterpret_cast<const float4*>(Cproj + (size_t)(d < 0 ? 0 : d) * 128);
    float* Hr = H + (size_t)(d < 0 ? 0 : d) * 128;

#pragma unroll
    for (int nt = 0; nt < 16; nt++) {
        float c0 = acc[nt][0], c1 = acc[nt][1], c2 = acc[nt][2], c3 = acc[nt][3];
        float o0 = __shfl_xor_sync(0xffffffffu, c0, 1);
        float o1 = __shfl_xor_sync(0xffffffffu, c1, 1);
        float o2 = __shfl_xor_sync(0xffffffffu, c2, 1);
        float o3 = __shfl_xor_sync(0xffffffffu, c3, 1);
        if (d < 0) continue;
        float v0, v1, v2, v3;
        if (tig & 1) { v0 = o2; v1 = o3; v2 = c2; v3 = c3; }
        else         { v0 = c0; v1 = c1; v2 = o0; v3 = o1; }
        int col = colb0 + nt * 8;
        float4 av = Ar[col >> 2];
        float4 cv = Cr[col >> 2];
        v0 = fmaxf(v0 + av.x + cv.x, 0.f);
        v1 = fmaxf(v1 + av.y + cv.y, 0.f);
        v2 = fmaxf(v2 + av.z + cv.z, 0.f);
        v3 = fmaxf(v3 + av.w + cv.w, 0.f);
        asm volatile("red.global.add.v4.f32 [%0], {%1,%2,%3,%4};"
                     :: "l"(Hr + col), "f"(v0), "f"(v1), "f"(v2), "f"(v3)
                     : "memory");
    }
}

// ---------------- launch ----------------
extern "C" void kernel_launch(void* const* d_in, const int* in_sizes, int n_in,
                              void* d_out, int out_size) {
    const float* srcF   = (const float*)d_in[0];
    const float* spos   = (const float*)d_in[1];
    const float* dstF   = (const float*)d_in[2];
    const float* dpos   = (const float*)d_in[3];
    const float* src_w  = (const float*)d_in[4];
    const float* src_b  = (const float*)d_in[5];
    const float* dst_w  = (const float*)d_in[6];
    const float* dst_b  = (const float*)d_in[7];
    const float* dist_w = (const float*)d_in[8];
    const float* dist_b = (const float*)d_in[9];
    const float* w1     = (const float*)d_in[10];
    const float* b1     = (const float*)d_in[11];
    const float* w2     = (const float*)d_in[12];
    const float* b2     = (const float*)d_in[13];
    const float* lng    = (const float*)d_in[14];
    const float* lnb    = (const float*)d_in[15];
    const float* out_w  = (const float*)d_in[16];
    const float* out_b  = (const float*)d_in[17];
    const int*   esrc   = (const int*)d_in[18];
    const int*   edst   = (const int*)d_in[19];
    int E = in_sizes[18];
    float* out = (float*)d_out;

    float *pDstEnc, *pA, *pC, *pH;
    int* pDeg;
    uint32_t* pW1f;
    cudaGetSymbolAddress((void**)&pDstEnc, g_dst_enc);
    cudaGetSymbolAddress((void**)&pA, g_Aproj);
    cudaGetSymbolAddress((void**)&pC, g_Cproj);
    cudaGetSymbolAddress((void**)&pH, g_H);
    cudaGetSymbolAddress((void**)&pDeg, g_deg);
    cudaGetSymbolAddress((void**)&pW1f, g_W1frag);

    const int SMEM_F = (2 * 128 * PADH) * 4 + 16384 * 4;      // 135168 B
    const int SMEM_E = (16384 + 7 * 128) * 4;                 // 69120 B
    cudaFuncSetAttribute(fused2, cudaFuncAttributeMaxDynamicSharedMemorySize, SMEM_F);
    cudaFuncSetAttribute(edge_kernel, cudaFuncAttributeMaxDynamicSharedMemorySize, SMEM_E);

    cudaMemsetAsync(pH, 0, (size_t)D_N * F * sizeof(float));
    cudaMemsetAsync(pDeg, 0, (size_t)D_N * sizeof(int));
    prep_w1b<<<64, 256>>>(w1 + 128 * 128, pW1f);

    // src path: A = relu(srcF@src_w + src_b) @ W1a
    fused2<<<128, 256, SMEM_F>>>(srcF, src_w, src_b, nullptr, nullptr, nullptr,
                                 1, nullptr, 0, nullptr, nullptr,
                                 w1, nullptr, nullptr, 0, pA);
    // dst path: dstEnc = relu(dstF@dst_w + dst_b) (kept); C = dstEnc@W1c + b1
    fused2<<<128, 256, SMEM_F>>>(dstF, dst_w, dst_b, nullptr, nullptr, nullptr,
                                 1, pDstEnc, 0, nullptr, nullptr,
                                 w1 + 256 * 128, b1, nullptr, 0, pC);

    // per-edge hidden + scatter (tf32 tensor cores)
    int nb = (E + 127) / 128;
    edge_kernel<<<nb, 256, SMEM_E>>>(spos, dpos, esrc, edst, dist_w, dist_b,
                                     pW1f, pA, pC, pH, pDeg, E);

    // tail: agg = H@W2 + dstEnc + deg*b2 ; LN+relu ; out = relu(T@out_w+out_b+dstF)
    fused2<<<128, 256, SMEM_F>>>(pH, w2, nullptr, pDstEnc, pDeg, b2,
                                 0, nullptr, 1, lng, lnb,
                                 out_w, out_b, dstF, 1, out);
}